// round 11
// baseline (speedup 1.0000x reference)
#include <cuda_runtime.h>
#include <cstdint>

#define N_POI  100000
#define N_USER 20000
#define NNZ    300000
#define EMB    256

// Intermediate: msg = A_up @ pois_embs, [N_USER, EMB] fp32 (20.48 MB scratch).
__device__ float g_msg[(size_t)N_USER * EMB];

// ---------------------------------------------------------------------------
// Zero-fill (float4 grid-stride)
// ---------------------------------------------------------------------------
__global__ void zero_kernel(float4* __restrict__ p, int n4) {
    int i = blockIdx.x * blockDim.x + threadIdx.x;
    int stride = gridDim.x * blockDim.x;
    float4 z = make_float4(0.f, 0.f, 0.f, 0.f);
    for (; i < n4; i += stride) p[i] = z;
}

// Vectorized fp32 reduction into global memory (sm_90+).
__device__ __forceinline__ void red_add_v4(float* dst, float4 v) {
    asm volatile("red.global.add.v4.f32 [%0], {%1, %2, %3, %4};"
                 :: "l"(dst), "f"(v.x), "f"(v.y), "f"(v.z), "f"(v.w)
                 : "memory");
}

// L2-only (non-L1-allocating) float4 gather.
__device__ __forceinline__ float4 ldcg_v4(const float4* p) {
    float4 r;
    asm volatile("ld.global.cg.v4.f32 {%0, %1, %2, %3}, [%4];"
                 : "=f"(r.x), "=f"(r.y), "=f"(r.z), "=f"(r.w) : "l"(p));
    return r;
}

// ---------------------------------------------------------------------------
// Fused COO SpMM (scatter w/ vector atomics) + optional zero-fill side job.
// Blocks [0, zero_blocks) grid-stride zero `zero_ptr[0..zero_n4)`.
// Remaining blocks: 64 threads per 2 edges; each thread handles one float4
// slice of two edges (independent chains -> 2x MLP).
// ---------------------------------------------------------------------------
__global__ void spmm_fused_kernel(const int*   __restrict__ rows,
                                  const int*   __restrict__ cols,
                                  const float* __restrict__ vals,
                                  const float* __restrict__ dense,
                                  float*       __restrict__ out,
                                  int nnz,
                                  float4*      __restrict__ zero_ptr,
                                  int zero_n4,
                                  int zero_blocks) {
    if ((int)blockIdx.x < zero_blocks) {
        int i = blockIdx.x * blockDim.x + threadIdx.x;
        int stride = zero_blocks * blockDim.x;
        float4 z = make_float4(0.f, 0.f, 0.f, 0.f);
        for (; i < zero_n4; i += stride) zero_ptr[i] = z;
        return;
    }

    int t    = (blockIdx.x - zero_blocks) * blockDim.x + threadIdx.x;
    int pair = t >> 6;          // 64 threads per edge-pair
    int lane = t & 63;          // 0..63, 4 floats each

    int e0 = pair * 2;
    int e1 = e0 + 1;
    if (e0 >= nnz) return;
    bool has1 = (e1 < nnz);

    // Independent index loads (broadcast within warp, L1-friendly lines).
    int   r0 = __ldg(rows + e0);
    int   c0 = __ldg(cols + e0);
    float v0 = __ldg(vals + e0);
    int   r1 = has1 ? __ldg(rows + e1) : 0;
    int   c1 = has1 ? __ldg(cols + e1) : 0;
    float v1 = has1 ? __ldg(vals + e1) : 0.f;

    // Independent gathers (L2-only; no L1 reuse at these table sizes).
    const float4* src0 = reinterpret_cast<const float4*>(dense + (size_t)c0 * EMB) + lane;
    const float4* src1 = reinterpret_cast<const float4*>(dense + (size_t)c1 * EMB) + lane;
    float4 s0 = ldcg_v4(src0);
    float4 s1 = has1 ? ldcg_v4(src1) : make_float4(0.f, 0.f, 0.f, 0.f);

    float* dst0 = out + (size_t)r0 * EMB + lane * 4;
    red_add_v4(dst0, make_float4(v0 * s0.x, v0 * s0.y, v0 * s0.z, v0 * s0.w));

    if (has1) {
        float* dst1 = out + (size_t)r1 * EMB + lane * 4;
        red_add_v4(dst1, make_float4(v1 * s1.x, v1 * s1.y, v1 * s1.z, v1 * s1.w));
    }
}

// ---------------------------------------------------------------------------
// kernel_launch
// Inputs (metadata order):
//   0: pois_embs [N_POI*EMB] f32
//   1: up_rows [NNZ] i32   2: up_cols [NNZ] i32   3: up_vals [NNZ] f32
//   4: pu_rows [NNZ] i32   5: pu_cols [NNZ] i32   6: pu_vals [NNZ] f32
// Output: propag_pois_embs [N_POI*EMB] f32
// ---------------------------------------------------------------------------
extern "C" void kernel_launch(void* const* d_in, const int* in_sizes, int n_in,
                              void* d_out, int out_size) {
    const float* pois_embs = (const float*)d_in[0];
    const int*   up_rows   = (const int*)  d_in[1];
    const int*   up_cols   = (const int*)  d_in[2];
    const float* up_vals   = (const float*)d_in[3];
    const int*   pu_rows   = (const int*)  d_in[4];
    const int*   pu_cols   = (const int*)  d_in[5];
    const float* pu_vals   = (const float*)d_in[6];
    float*       out       = (float*)d_out;

    float* msg = nullptr;
    cudaGetSymbolAddress((void**)&msg, g_msg);

    // K1: zero the (small) intermediate.
    {
        int n4 = (N_USER * EMB) / 4;
        zero_kernel<<<2048, 256>>>((float4*)msg, n4);
    }

    const int PAIRS       = (NNZ + 1) / 2;
    const int EDGE_BLOCKS = (int)(((long long)PAIRS * 64 + 255) / 256);
    const int ZB          = 4096;   // zero side-job blocks for `out`

    // K2: hop 1 (msg = A_up @ pois_embs) fused with zeroing of `out`.
    spmm_fused_kernel<<<EDGE_BLOCKS + ZB, 256>>>(
        up_rows, up_cols, up_vals, pois_embs, msg, NNZ,
        (float4*)out, (N_POI * EMB) / 4, ZB);

    // K3: hop 2 (out = A_pu @ msg), no side job.
    spmm_fused_kernel<<<EDGE_BLOCKS, 256>>>(
        pu_rows, pu_cols, pu_vals, msg, out, NNZ,
        nullptr, 0, 0);
}

// round 12
// speedup vs baseline: 1.0142x; 1.0142x over previous
#include <cuda_runtime.h>
#include <cstdint>

#define N_POI  100000
#define N_USER 20000
#define NNZ    300000
#define EMB    256

// Intermediate: msg = A_up @ pois_embs, [N_USER, EMB] fp32 (20.48 MB scratch).
__device__ float g_msg[(size_t)N_USER * EMB];

// ---------------------------------------------------------------------------
// Zero-fill (float4 grid-stride)
// ---------------------------------------------------------------------------
__global__ void zero_kernel(float4* __restrict__ p, int n4) {
    int i = blockIdx.x * blockDim.x + threadIdx.x;
    int stride = gridDim.x * blockDim.x;
    float4 z = make_float4(0.f, 0.f, 0.f, 0.f);
    for (; i < n4; i += stride) p[i] = z;
}

// Vectorized fp32 reduction into global memory (sm_90+).
__device__ __forceinline__ void red_add_v4(float* dst, float4 v) {
    asm volatile("red.global.add.v4.f32 [%0], {%1, %2, %3, %4};"
                 :: "l"(dst), "f"(v.x), "f"(v.y), "f"(v.z), "f"(v.w)
                 : "memory");
}

// L2-only (non-L1-allocating) float4 gather.
__device__ __forceinline__ float4 ldcg_v4(const float4* p) {
    float4 r;
    asm volatile("ld.global.cg.v4.f32 {%0, %1, %2, %3}, [%4];"
                 : "=f"(r.x), "=f"(r.y), "=f"(r.z), "=f"(r.w) : "l"(p));
    return r;
}

// ---------------------------------------------------------------------------
// Fused COO SpMM (scatter w/ vector atomics) + optional zero-fill side job.
// Blocks [0, zero_blocks) grid-stride zero `zero_ptr[0..zero_n4)`.
// Remaining blocks: 64 threads per 2 edges; each thread handles one float4
// slice of two edges (independent chains -> 2x MLP).
// ---------------------------------------------------------------------------
__global__ void spmm_fused_kernel(const int*   __restrict__ rows,
                                  const int*   __restrict__ cols,
                                  const float* __restrict__ vals,
                                  const float* __restrict__ dense,
                                  float*       __restrict__ out,
                                  int nnz,
                                  float4*      __restrict__ zero_ptr,
                                  int zero_n4,
                                  int zero_blocks) {
    if ((int)blockIdx.x < zero_blocks) {
        int i = blockIdx.x * blockDim.x + threadIdx.x;
        int stride = zero_blocks * blockDim.x;
        float4 z = make_float4(0.f, 0.f, 0.f, 0.f);
        for (; i < zero_n4; i += stride) zero_ptr[i] = z;
        return;
    }

    int t    = (blockIdx.x - zero_blocks) * blockDim.x + threadIdx.x;
    int pair = t >> 6;          // 64 threads per edge-pair
    int lane = t & 63;          // 0..63, 4 floats each

    int e0 = pair * 2;
    int e1 = e0 + 1;
    if (e0 >= nnz) return;
    bool has1 = (e1 < nnz);

    // Independent index loads (broadcast within warp, L1-friendly lines).
    int   r0 = __ldg(rows + e0);
    int   c0 = __ldg(cols + e0);
    float v0 = __ldg(vals + e0);
    int   r1 = has1 ? __ldg(rows + e1) : 0;
    int   c1 = has1 ? __ldg(cols + e1) : 0;
    float v1 = has1 ? __ldg(vals + e1) : 0.f;

    // Independent gathers (L2-only; no L1 reuse at these table sizes).
    const float4* src0 = reinterpret_cast<const float4*>(dense + (size_t)c0 * EMB) + lane;
    const float4* src1 = reinterpret_cast<const float4*>(dense + (size_t)c1 * EMB) + lane;
    float4 s0 = ldcg_v4(src0);
    float4 s1 = has1 ? ldcg_v4(src1) : make_float4(0.f, 0.f, 0.f, 0.f);

    float* dst0 = out + (size_t)r0 * EMB + lane * 4;
    red_add_v4(dst0, make_float4(v0 * s0.x, v0 * s0.y, v0 * s0.z, v0 * s0.w));

    if (has1) {
        float* dst1 = out + (size_t)r1 * EMB + lane * 4;
        red_add_v4(dst1, make_float4(v1 * s1.x, v1 * s1.y, v1 * s1.z, v1 * s1.w));
    }
}

// ---------------------------------------------------------------------------
// kernel_launch
// Inputs (metadata order):
//   0: pois_embs [N_POI*EMB] f32
//   1: up_rows [NNZ] i32   2: up_cols [NNZ] i32   3: up_vals [NNZ] f32
//   4: pu_rows [NNZ] i32   5: pu_cols [NNZ] i32   6: pu_vals [NNZ] f32
// Output: propag_pois_embs [N_POI*EMB] f32
// ---------------------------------------------------------------------------
extern "C" void kernel_launch(void* const* d_in, const int* in_sizes, int n_in,
                              void* d_out, int out_size) {
    const float* pois_embs = (const float*)d_in[0];
    const int*   up_rows   = (const int*)  d_in[1];
    const int*   up_cols   = (const int*)  d_in[2];
    const float* up_vals   = (const float*)d_in[3];
    const int*   pu_rows   = (const int*)  d_in[4];
    const int*   pu_cols   = (const int*)  d_in[5];
    const float* pu_vals   = (const float*)d_in[6];
    float*       out       = (float*)d_out;

    float* msg = nullptr;
    cudaGetSymbolAddress((void**)&msg, g_msg);

    // K1: zero the (small) intermediate.
    {
        int n4 = (N_USER * EMB) / 4;
        zero_kernel<<<2048, 256>>>((float4*)msg, n4);
    }

    const int PAIRS       = (NNZ + 1) / 2;
    const int EDGE_BLOCKS = (int)(((long long)PAIRS * 64 + 255) / 256);
    const int ZB          = 4096;   // zero side-job blocks for `out`

    // K2: hop 1 (msg = A_up @ pois_embs) fused with zeroing of `out`.
    spmm_fused_kernel<<<EDGE_BLOCKS + ZB, 256>>>(
        up_rows, up_cols, up_vals, pois_embs, msg, NNZ,
        (float4*)out, (N_POI * EMB) / 4, ZB);

    // K3: hop 2 (out = A_pu @ msg), no side job.
    spmm_fused_kernel<<<EDGE_BLOCKS, 256>>>(
        pu_rows, pu_cols, pu_vals, msg, out, NNZ,
        nullptr, 0, 0);
}